// round 16
// baseline (speedup 1.0000x reference)
#include <cuda_runtime.h>
#include <cstdint>

// ============================================================================
// Stacked LSTM (H1=51, H2=1), B=2048, T=1024 (+F=64 autoregressive steps).
//
// Round 16: unit-split teams at V=4 -> 2 warps per SMSP.
//   - Block = team = 2 warps serving 4 batch elements. Warp0 owns h1-units
//     0..25(+), warp1 units 26..50(+pad). Lane = ONE unit x 4 elements.
//   - 512 blocks -> ~3.5 blocks/SM -> ~2 warps/SMSP: team A's barrier and
//     latency stalls hide under team B's FFMA2 stream (R15 failed at 1/SMSP).
//   - Per-warp weight stream = half table (~166 wavefronts); fma floor
//     unchanged (chip-wide); crossbar ~ R14 level but now overlapped.
//   - h1 via double-buffered smem + one __syncthreads per step.
//   - LSTM2: 4 elems x 4 gates = 16 lanes full 51-dot from smem (mirrored in
//     high lanes, redundant in both warps, bit-identical), deferred 1 step.
//   - FFMA2 packed gate pairs, tanh.approx activations.
// ============================================================================

#define FULLMASK 0xffffffffu
#define H1 51
#define KP 52

typedef unsigned long long ull;

#define FMA2(d, a, b, c) \
    asm("fma.rn.f32x2 %0, %1, %2, %3;" : "=l"(d) : "l"(a), "l"(b), "l"(c))

__device__ __forceinline__ ull pack2(float lo, float hi) {
    ull r; asm("mov.b64 %0, {%1, %2};" : "=l"(r) : "f"(lo), "f"(hi)); return r;
}
__device__ __forceinline__ ull dup2(float x) {
    ull r; asm("mov.b64 %0, {%1, %1};" : "=l"(r) : "f"(x)); return r;
}
__device__ __forceinline__ float2 unpack2(ull v) {
    float2 r; asm("mov.b64 {%0, %1}, %2;" : "=f"(r.x), "=f"(r.y) : "l"(v)); return r;
}

__device__ __forceinline__ float ftanh(float x) {
    float r; asm("tanh.approx.f32 %0, %1;" : "=f"(r) : "f"(x)); return r;
}
__device__ __forceinline__ float fsig(float x) {
    return fmaf(0.5f, ftanh(0.5f * x), 0.5f);
}

__global__ void __launch_bounds__(64, 1) lstm_seq_kernel(
    const float* __restrict__ input,   // [B, T]
    const float* __restrict__ Wih1,    // [204, 1]
    const float* __restrict__ Whh1,    // [204, 51]
    const float* __restrict__ bih1,    // [204]
    const float* __restrict__ bhh1,    // [204]
    const float* __restrict__ Wih2,    // [4, 51]
    const float* __restrict__ Whh2,    // [4, 1]
    const float* __restrict__ bih2,    // [4]
    const float* __restrict__ bhh2,    // [4]
    float* __restrict__ out,           // [B, T+F]
    int T, int TF)
{
    // W1s[k][u]: float4 gate weights (i,f,g,o), row 51 / col 51 zero pad.
    __shared__ float4 W1s[KP * KP];    // 43264 B
    __shared__ float4 W2s[4 * 13];     //   832 B  Wih2[g][k] chunked
    __shared__ float4 Hs[2][4][13];    //  1664 B  [buf][elem][chunk] h1
                                       // total 45760 B < 48KB static limit

    const int tid = threadIdx.x;

    // ---- init shared ----
    for (int idx = tid; idx < KP * KP; idx += 64) {
        int k = idx / KP, u = idx % KP;
        float4 w = make_float4(0.f, 0.f, 0.f, 0.f);
        if (k < H1 && u < H1) {
            w.x = Whh1[(0 * H1 + u) * H1 + k];
            w.y = Whh1[(1 * H1 + u) * H1 + k];
            w.z = Whh1[(2 * H1 + u) * H1 + k];
            w.w = Whh1[(3 * H1 + u) * H1 + k];
        }
        W1s[idx] = w;
    }
    for (int idx = tid; idx < 4 * 13; idx += 64) {
        int g = idx / 13, c = idx % 13;
        float4 w = make_float4(0.f, 0.f, 0.f, 0.f);
        float* wf = (float*)&w;
        for (int j = 0; j < 4; j++) {
            int k = c * 4 + j;
            if (k < H1) wf[j] = Wih2[g * H1 + k];
        }
        W2s[idx] = w;
    }
    for (int idx = tid; idx < 2 * 4 * 13; idx += 64)
        ((float4*)Hs)[idx] = make_float4(0.f, 0.f, 0.f, 0.f);
    __syncthreads();

    const ulonglong2* __restrict__ W1u = reinterpret_cast<const ulonglong2*>(W1s);

    const int lane = tid & 31;
    const int wid  = tid >> 5;
    const int uraw = wid * 26 + lane;       // warp0: 0..31, warp1: 26..57
    const bool real = uraw < H1;            // owns a real unit
    const int  u    = real ? uraw : H1;     // pad column 51 otherwise

    // ---- per-unit input weights / bias (zero for pad lanes) ----
    float Wi[4], bi[4];
#pragma unroll
    for (int g = 0; g < 4; g++) {
        int ui = real ? uraw : 0;
        float wv = Wih1[g * H1 + ui];
        float bv = bih1[g * H1 + ui] + bhh1[g * H1 + ui];
        Wi[g] = real ? wv : 0.f;
        bi[g] = real ? bv : 0.f;
    }
    const ull Wip0 = pack2(Wi[0], Wi[1]), Wip1 = pack2(Wi[2], Wi[3]);
    const ull bp0  = pack2(bi[0], bi[1]), bp1  = pack2(bi[2], bi[3]);

    // LSTM2 lane mapping: 4 elems x 4 gates = 16 lanes, mirrored in 16..31
    const int e2 = (lane >> 2) & 3;
    const int g2 = lane & 3;
    const float W2h_l = Whh2[g2];
    const float b2_l  = bih2[g2] + bhh2[g2];

    // ---- state ----
    float c1[4] = {0.f, 0.f, 0.f, 0.f};
    float h2v = 0.f, c2v = 0.f;     // LSTM2 state (identical in both warps)

    const int bbase = blockIdx.x * 4;
    const float* inp[4];
#pragma unroll
    for (int e = 0; e < 4; e++) inp[e] = input + (size_t)(bbase + e) * T;
    float* outw = (wid == 0 && lane < 16 && g2 == 0)
                ? out + (size_t)(bbase + e2) * TF : nullptr;

#pragma unroll 1
    for (int t = 0; t <= TF; t++) {
        const int pb = (t & 1) ^ 1;        // buffer holding h1(t-1)

        // ---- deferred LSTM2 for step t-1 (reads h1(t-1); overlaps k-loop
        //      in the main phase; supplies x=h2 in the future phase) ----
        if (t > 0) {
            float acc0 = 0.f, acc1 = 0.f;
#pragma unroll
            for (int c = 0; c < 13; c++) {
                float4 hv = Hs[pb][e2][c];
                float4 wv = W2s[g2 * 13 + c];
                acc0 = fmaf(hv.x, wv.x, fmaf(hv.y, wv.y, acc0));
                acc1 = fmaf(hv.z, wv.z, fmaf(hv.w, wv.w, acc1));
            }
            float pre = acc0 + acc1 + W2h_l * h2v + b2_l;
            const int base = lane & ~3;
            float pi = __shfl_sync(FULLMASK, pre, base + 0);
            float pf = __shfl_sync(FULLMASK, pre, base + 1);
            float pg = __shfl_sync(FULLMASK, pre, base + 2);
            float po = __shfl_sync(FULLMASK, pre, base + 3);
            float i2 = fsig(pi), f2 = fsig(pf), gg = ftanh(pg), o2 = fsig(po);
            c2v = f2 * c2v + i2 * gg;
            h2v = o2 * ftanh(c2v);
            if (outw) outw[t - 1] = h2v;
        }
        if (t == TF) break;

        // ---- LSTM1 input: data in main phase, own h2 in future phase ----
        float x[4];
        if (t < T) {
#pragma unroll
            for (int e = 0; e < 4; e++) x[e] = __ldg(inp[e] + t);
        } else {
#pragma unroll
            for (int e = 0; e < 4; e++)
                x[e] = __shfl_sync(FULLMASK, h2v, e << 2);
        }

        // ---- gate accumulators: pair0=(i,f), pair1=(g,o) per element ----
        ull a0[4], a1[4];
#pragma unroll
        for (int e = 0; e < 4; e++) {
            ull d = dup2(x[e]);
            FMA2(a0[e], d, Wip0, bp0);
            FMA2(a1[e], d, Wip1, bp1);
        }

        // ---- recurrent dot: 13 chunks x 4 k; h broadcast, own W column ----
#pragma unroll
        for (int kc = 0; kc < 13; kc++) {
            float4 hv[4];
#pragma unroll
            for (int e = 0; e < 4; e++) hv[e] = Hs[pb][e][kc];
#pragma unroll
            for (int j = 0; j < 4; j++) {
                const int k = kc * 4 + j;
                const ulonglong2 wv = W1u[k * KP + u];
#pragma unroll
                for (int e = 0; e < 4; e++) {
                    float hk = (j == 0) ? hv[e].x : (j == 1) ? hv[e].y
                             : (j == 2) ? hv[e].z : hv[e].w;
                    ull d = dup2(hk);
                    FMA2(a0[e], d, wv.x, a0[e]);
                    FMA2(a1[e], d, wv.y, a1[e]);
                }
            }
        }

        // ---- activations + cell update + publish h(t) ----
        const int cb = t & 1;
#pragma unroll
        for (int e = 0; e < 4; e++) {
            float2 v0 = unpack2(a0[e]), v1 = unpack2(a1[e]);
            float i = fsig(v0.x), f = fsig(v0.y);
            float g = ftanh(v1.x), o = fsig(v1.y);
            c1[e] = f * c1[e] + i * g;
            float h = o * ftanh(c1[e]);
            if (real) ((float*)&Hs[cb][e][0])[uraw] = h;
        }
        __syncthreads();   // h(t) visible to both warps before iter t+1
    }
}

extern "C" void kernel_launch(void* const* d_in, const int* in_sizes, int n_in,
                              void* d_out, int out_size) {
    const float* input = (const float*)d_in[0];
    const float* Wih1  = (const float*)d_in[1];
    const float* Whh1  = (const float*)d_in[2];
    const float* bih1  = (const float*)d_in[3];
    const float* bhh1  = (const float*)d_in[4];
    const float* Wih2  = (const float*)d_in[5];
    const float* Whh2  = (const float*)d_in[6];
    const float* bih2  = (const float*)d_in[7];
    const float* bhh2  = (const float*)d_in[8];
    float* out = (float*)d_out;

    const int B  = 2048;
    const int T  = in_sizes[0] / B;     // 1024
    const int TF = out_size / B;        // 1088

    // 1 team (2 warps) per block, 4 batch elements per team -> 512 blocks
    lstm_seq_kernel<<<B / 4, 64>>>(input, Wih1, Whh1, bih1, bhh1,
                                   Wih2, Whh2, bih2, bhh2,
                                   out, T, TF);
}

// round 17
// speedup vs baseline: 1.1030x; 1.1030x over previous
#include <cuda_runtime.h>
#include <cstdint>

// ============================================================================
// Stacked LSTM (H1=51, H2=1), B=2048, T=1024 (+F=64 autoregressive steps).
//
// Round 17: R14 base + cross-step software pipelining of the weight stream.
//   - V=4 elems/warp, 2 independent warps/block, 256 blocks (R14 layout:
//     both floors — fma 1632 cyc/SMSP, crossbar ~1800 cyc/SM — balanced).
//   - Weight double-buffer in registers: k-loop refills chunk kc+2 after
//     consuming kc; refills at kc=11/12 prefetch NEXT step's chunks 1/0,
//     issued before the MUFU activation tail so their latency hides there.
//   - k=51 pad row eliminated (chunk 12 = 3 k's); W1s row 51 reused to
//     store W2s (keeps static smem at 46.6KB).
//   - x inputs batched as float4 per 4 steps, double-buffered.
//   - FFMA2 packed gate pairs, tanh.approx, deferred LSTM2 (as R14).
// ============================================================================

#define FULLMASK 0xffffffffu
#define H1 51
#define KP 52

typedef unsigned long long ull;

#define FMA2(d, a, b, c) \
    asm("fma.rn.f32x2 %0, %1, %2, %3;" : "=l"(d) : "l"(a), "l"(b), "l"(c))

__device__ __forceinline__ ull pack2(float lo, float hi) {
    ull r; asm("mov.b64 %0, {%1, %2};" : "=l"(r) : "f"(lo), "f"(hi)); return r;
}
__device__ __forceinline__ ull dup2(float x) {
    ull r; asm("mov.b64 %0, {%1, %1};" : "=l"(r) : "f"(x)); return r;
}
__device__ __forceinline__ float2 unpack2(ull v) {
    float2 r; asm("mov.b64 {%0, %1}, %2;" : "=f"(r.x), "=f"(r.y) : "l"(v)); return r;
}

__device__ __forceinline__ float ftanh(float x) {
    float r; asm("tanh.approx.f32 %0, %1;" : "=f"(r) : "f"(x)); return r;
}
__device__ __forceinline__ float fsig(float x) {
    return fmaf(0.5f, ftanh(0.5f * x), 0.5f);
}

__global__ void __launch_bounds__(64, 1) lstm_seq_kernel(
    const float* __restrict__ input,   // [B, T]
    const float* __restrict__ Wih1,    // [204, 1]
    const float* __restrict__ Whh1,    // [204, 51]
    const float* __restrict__ bih1,    // [204]
    const float* __restrict__ bhh1,    // [204]
    const float* __restrict__ Wih2,    // [4, 51]
    const float* __restrict__ Whh2,    // [4, 1]
    const float* __restrict__ bih2,    // [4]
    const float* __restrict__ bhh2,    // [4]
    float* __restrict__ out,           // [B, T+F]
    int T, int TF)
{
    // W1s[k][u]: float4 gate weights (i,f,g,o). Rows k=0..50 are real
    // (col 51 zero pad for the uB lanes). Row 51 is never read as weights
    // (chunk 12 consumes only k=48..50) and stores W2s (Wih2 chunked).
    __shared__ float4 W1s[KP * KP];    // 43264 B
    __shared__ float4 Hs[2][4][13];    //  3328 B [warp][elem][chunk] h1
                                       // total 46592 B < 48KB static limit

    const int tid = threadIdx.x;

    // ---- init shared ----
    for (int idx = tid; idx < KP * KP; idx += 64) {
        int k = idx / KP, u = idx % KP;
        if (k >= H1) continue;                   // row 51 written below
        float4 wv = make_float4(0.f, 0.f, 0.f, 0.f);
        if (u < H1) {
            wv.x = Whh1[(0 * H1 + u) * H1 + k];
            wv.y = Whh1[(1 * H1 + u) * H1 + k];
            wv.z = Whh1[(2 * H1 + u) * H1 + k];
            wv.w = Whh1[(3 * H1 + u) * H1 + k];
        }
        W1s[idx] = wv;
    }
    // W2s lives in W1s row 51: entry [g*13+c] = Wih2[g][4c..4c+3]
    for (int idx = tid; idx < KP; idx += 64) {
        float4 wv = make_float4(0.f, 0.f, 0.f, 0.f);
        if (idx < 4 * 13) {
            int g = idx / 13, c = idx % 13;
            float* wf = (float*)&wv;
            for (int j = 0; j < 4; j++) {
                int k = c * 4 + j;
                if (k < H1) wf[j] = Wih2[g * H1 + k];
            }
        }
        W1s[H1 * KP + idx] = wv;
    }
    for (int idx = tid; idx < 2 * 4 * 13; idx += 64)
        ((float4*)Hs)[idx] = make_float4(0.f, 0.f, 0.f, 0.f);
    __syncthreads();

    const ulonglong2* __restrict__ W1u = reinterpret_cast<const ulonglong2*>(W1s);
    const float4*     __restrict__ W2s = &W1s[H1 * KP];

    const int lane = tid & 31;
    const int w    = tid >> 5;
    const int warp = blockIdx.x * 2 + w;

    const int  uA   = lane;
    const bool hasB = (lane + 32) < H1;          // lanes 0..18
    const int  uB   = hasB ? (lane + 32) : H1;   // pad col 51 for 19..31
    const int  uBw  = hasB ? (lane + 32) : 0;

    // ---- per-lane constants ----
    float WiA[4], WiB[4], bA[4], bB[4];
#pragma unroll
    for (int g = 0; g < 4; g++) {
        WiA[g] = Wih1[g * H1 + uA];
        bA[g]  = bih1[g * H1 + uA] + bhh1[g * H1 + uA];
        float wib = Wih1[g * H1 + uBw];
        float bb  = bih1[g * H1 + uBw] + bhh1[g * H1 + uBw];
        WiB[g] = hasB ? wib : 0.f;
        bB[g]  = hasB ? bb  : 0.f;
    }
    const ull WiAp0 = pack2(WiA[0], WiA[1]), WiAp1 = pack2(WiA[2], WiA[3]);
    const ull WiBp0 = pack2(WiB[0], WiB[1]), WiBp1 = pack2(WiB[2], WiB[3]);
    const ull bAp0  = pack2(bA[0],  bA[1]),  bAp1  = pack2(bA[2],  bA[3]);
    const ull bBp0  = pack2(bB[0],  bB[1]),  bBp1  = pack2(bB[2],  bB[3]);

    // LSTM2 lane mapping: 4 elems x 4 gates in lanes 0..15, mirrored 16..31
    const int e2 = (lane >> 2) & 3;
    const int g2 = lane & 3;
    const float W2h_l = Whh2[g2];
    const float b2_l  = bih2[g2] + bhh2[g2];

    // ---- state ----
    float c1A[4] = {0.f, 0.f, 0.f, 0.f};
    float c1B[4] = {0.f, 0.f, 0.f, 0.f};
    float h2v = 0.f, c2v = 0.f;

    const int bbase = warp * 4;
    const float* inp[4];
#pragma unroll
    for (int e = 0; e < 4; e++) inp[e] = input + (size_t)(bbase + e) * T;
    float* outw = (lane < 16 && g2 == 0)
                ? out + (size_t)(bbase + e2) * TF : nullptr;

    // ---- weight register double-buffer ----
    ulonglong2 wbA[2][4], wbB[2][4];
#define LOAD_CHUNK(slot, c, jmax)                                         \
    do {                                                                  \
        _Pragma("unroll")                                                 \
        for (int j = 0; j < (jmax); j++) {                                \
            wbA[slot][j] = W1u[((c) * 4 + j) * KP + uA];                  \
            wbB[slot][j] = W1u[((c) * 4 + j) * KP + uB];                  \
        }                                                                 \
    } while (0)

    LOAD_CHUNK(0, 0, 4);
    LOAD_CHUNK(1, 1, 4);

    // ---- x input double-buffer (float4 per 4 steps) ----
    float4 xcur[4], xnxt[4];
#pragma unroll
    for (int e = 0; e < 4; e++)
        xnxt[e] = *(const float4*)(inp[e]);

#pragma unroll 1
    for (int t = 0; t <= TF; t++) {
        // ---- deferred LSTM2 for step t-1 (overlaps next k-loop in the
        //      main phase; supplies x=h2 in the future phase) ----
        if (t > 0) {
            float acc0 = 0.f, acc1 = 0.f;
#pragma unroll
            for (int c = 0; c < 13; c++) {
                float4 hv = Hs[w][e2][c];
                float4 wv = W2s[g2 * 13 + c];
                acc0 = fmaf(hv.x, wv.x, fmaf(hv.y, wv.y, acc0));
                acc1 = fmaf(hv.z, wv.z, fmaf(hv.w, wv.w, acc1));
            }
            float pre = acc0 + acc1 + W2h_l * h2v + b2_l;
            const int base = lane & ~3;
            float pi = __shfl_sync(FULLMASK, pre, base + 0);
            float pf = __shfl_sync(FULLMASK, pre, base + 1);
            float pg = __shfl_sync(FULLMASK, pre, base + 2);
            float po = __shfl_sync(FULLMASK, pre, base + 3);
            float i2 = fsig(pi), f2 = fsig(pf), gg = ftanh(pg), o2 = fsig(po);
            c2v = f2 * c2v + i2 * gg;
            h2v = o2 * ftanh(c2v);
            if (outw) outw[t - 1] = h2v;
        }
        if (t == TF) break;

        // ---- LSTM1 input ----
        float x[4];
        if (t < T) {
            if ((t & 3) == 0) {
#pragma unroll
                for (int e = 0; e < 4; e++) xcur[e] = xnxt[e];
                if (t + 4 < T) {
#pragma unroll
                    for (int e = 0; e < 4; e++)
                        xnxt[e] = *(const float4*)(inp[e] + t + 4);
                }
            }
            const int q = t & 3;
#pragma unroll
            for (int e = 0; e < 4; e++)
                x[e] = (q == 0) ? xcur[e].x : (q == 1) ? xcur[e].y
                     : (q == 2) ? xcur[e].z : xcur[e].w;
        } else {
#pragma unroll
            for (int e = 0; e < 4; e++)
                x[e] = __shfl_sync(FULLMASK, h2v, e << 2);
        }

        // ---- gate accumulators: pair0=(i,f), pair1=(g,o) ----
        ull aA0[4], aA1[4], aB0[4], aB1[4];
#pragma unroll
        for (int e = 0; e < 4; e++) {
            ull d = dup2(x[e]);
            FMA2(aA0[e], d, WiAp0, bAp0);
            FMA2(aA1[e], d, WiAp1, bAp1);
            FMA2(aB0[e], d, WiBp0, bBp0);
            FMA2(aB1[e], d, WiBp1, bBp1);
        }

        // ---- recurrent dot: 13 chunks; consume wb[slot], refill kc+2.
        //      Refills at kc=11/12 prefetch NEXT step's chunks 1/0 and are
        //      issued before the activation tail (latency hides there). ----
#pragma unroll
        for (int kc = 0; kc < 13; kc++) {
            const int slot = kc & 1;
            float4 hv[4];
#pragma unroll
            for (int e = 0; e < 4; e++) hv[e] = Hs[w][e][kc];
            const int jmax = (kc == 12) ? 3 : 4;   // k=51 pad row skipped
#pragma unroll
            for (int j = 0; j < 4; j++) {
                if (j >= jmax) break;
                const ulonglong2 wvA = wbA[slot][j];
                const ulonglong2 wvB = wbB[slot][j];
#pragma unroll
                for (int e = 0; e < 4; e++) {
                    float hk = (j == 0) ? hv[e].x : (j == 1) ? hv[e].y
                             : (j == 2) ? hv[e].z : hv[e].w;
                    ull d = dup2(hk);
                    FMA2(aA0[e], d, wvA.x, aA0[e]);
                    FMA2(aA1[e], d, wvA.y, aA1[e]);
                    FMA2(aB0[e], d, wvB.x, aB0[e]);
                    FMA2(aB1[e], d, wvB.y, aB1[e]);
                }
            }
            if (kc <= 10) {
                if (kc + 2 == 12) LOAD_CHUNK(slot, 12, 3);
                else              LOAD_CHUNK(slot, kc + 2, 4);
            } else if (kc == 11) {
                LOAD_CHUNK(1, 1, 4);   // next step chunk 1
            } else {
                LOAD_CHUNK(0, 0, 4);   // next step chunk 0
            }
        }

        // ---- activations + cell update (MUFU tail overlaps prefetches) ----
        float hA[4], hB[4];
#pragma unroll
        for (int e = 0; e < 4; e++) {
            float2 vA0 = unpack2(aA0[e]), vA1 = unpack2(aA1[e]);
            float2 vB0 = unpack2(aB0[e]), vB1 = unpack2(aB1[e]);
            {
                float i = fsig(vA0.x), f = fsig(vA0.y);
                float g = ftanh(vA1.x), o = fsig(vA1.y);
                c1A[e] = f * c1A[e] + i * g;
                hA[e] = o * ftanh(c1A[e]);
            }
            {
                float i = fsig(vB0.x), f = fsig(vB0.y);
                float g = ftanh(vB1.x), o = fsig(vB1.y);
                c1B[e] = f * c1B[e] + i * g;
                hB[e] = o * ftanh(c1B[e]);
            }
        }

        // ---- publish h(t) (single-buffered Hs: fence on both sides) ----
        __syncwarp();
#pragma unroll
        for (int e = 0; e < 4; e++) {
            float* hrow = (float*)&Hs[w][e][0];
            hrow[lane] = hA[e];
            if (hasB) hrow[lane + 32] = hB[e];
        }
        __syncwarp();
    }
}

extern "C" void kernel_launch(void* const* d_in, const int* in_sizes, int n_in,
                              void* d_out, int out_size) {
    const float* input = (const float*)d_in[0];
    const float* Wih1  = (const float*)d_in[1];
    const float* Whh1  = (const float*)d_in[2];
    const float* bih1  = (const float*)d_in[3];
    const float* bhh1  = (const float*)d_in[4];
    const float* Wih2  = (const float*)d_in[5];
    const float* Whh2  = (const float*)d_in[6];
    const float* bih2  = (const float*)d_in[7];
    const float* bhh2  = (const float*)d_in[8];
    float* out = (float*)d_out;

    const int B  = 2048;
    const int T  = in_sizes[0] / B;     // 1024
    const int TF = out_size / B;        // 1088

    // 2 independent warps/block, 4 batch elements/warp -> 256 blocks
    lstm_seq_kernel<<<B / 8, 64>>>(input, Wih1, Whh1, bih1, bhh1,
                                   Wih2, Whh2, bih2, bhh2,
                                   out, T, TF);
}